// round 2
// baseline (speedup 1.0000x reference)
#include <cuda_runtime.h>
#include <cuda_bf16.h>
#include <cstdint>

// Problem constants
#define B_   2
#define S_   4096
#define D_   512
#define H_   8
#define DK_  64
#define BHS  (B_*H_*S_*DK_)   // 4,194,304 elements per head-layout tensor

// Scratch (head layout [b][h][s][dk])
__device__ float g_qh[BHS];
__device__ float g_kh[BHS];
__device__ float g_vh[BHS];
__device__ float g_oh[BHS];

// ---------------------------------------------------------------------------
// QKV projection: X[8192,512] @ W[512,512] -> head layout [b][h][s][dk]
// BM=64, BN=64, BK=32, 256 threads, 4x4 per thread.
// ---------------------------------------------------------------------------
__global__ void proj_qkv_kernel(const float* __restrict__ X,
                                const float* __restrict__ W,
                                int which)
{
    __shared__ float As[64][33];   // [row][k]
    __shared__ float Bs[32][68];   // [k][col], stride 68 keeps float4 aligned

    const int tid = threadIdx.x;
    const int tx = tid & 15;
    const int ty = tid >> 4;
    const int m0 = blockIdx.x * 64;
    const int n0 = blockIdx.y * 64;

    float acc[4][4];
#pragma unroll
    for (int i = 0; i < 4; i++)
#pragma unroll
        for (int j = 0; j < 4; j++) acc[i][j] = 0.f;

    for (int k0 = 0; k0 < 512; k0 += 32) {
        // Load A tile 64x32
        {
            const int r = tid >> 3;
            const int c = (tid & 7) * 4;
#pragma unroll
            for (int rr = 0; rr < 64; rr += 32) {
                float4 v = *reinterpret_cast<const float4*>(
                    &X[(size_t)(m0 + r + rr) * 512 + k0 + c]);
                As[r + rr][c + 0] = v.x;
                As[r + rr][c + 1] = v.y;
                As[r + rr][c + 2] = v.z;
                As[r + rr][c + 3] = v.w;
            }
        }
        // Load B tile 32x64
        {
            const int r = tid >> 4;
            const int c = (tid & 15) * 4;
#pragma unroll
            for (int rr = 0; rr < 32; rr += 16) {
                float4 v = *reinterpret_cast<const float4*>(
                    &W[(size_t)(k0 + r + rr) * 512 + n0 + c]);
                *reinterpret_cast<float4*>(&Bs[r + rr][c]) = v;
            }
        }
        __syncthreads();

#pragma unroll 8
        for (int kk = 0; kk < 32; kk++) {
            float a0 = As[ty * 4 + 0][kk];
            float a1 = As[ty * 4 + 1][kk];
            float a2 = As[ty * 4 + 2][kk];
            float a3 = As[ty * 4 + 3][kk];
            float4 b4 = *reinterpret_cast<const float4*>(&Bs[kk][tx * 4]);
            acc[0][0] += a0 * b4.x; acc[0][1] += a0 * b4.y; acc[0][2] += a0 * b4.z; acc[0][3] += a0 * b4.w;
            acc[1][0] += a1 * b4.x; acc[1][1] += a1 * b4.y; acc[1][2] += a1 * b4.z; acc[1][3] += a1 * b4.w;
            acc[2][0] += a2 * b4.x; acc[2][1] += a2 * b4.y; acc[2][2] += a2 * b4.z; acc[2][3] += a2 * b4.w;
            acc[3][0] += a3 * b4.x; acc[3][1] += a3 * b4.y; acc[3][2] += a3 * b4.z; acc[3][3] += a3 * b4.w;
        }
        __syncthreads();
    }

    float* Oh = (which == 0) ? g_qh : (which == 1) ? g_kh : g_vh;
    const int h = n0 >> 6;      // n0 is a multiple of 64
#pragma unroll
    for (int i = 0; i < 4; i++) {
        const int m = m0 + ty * 4 + i;
        const int b = m >> 12;
        const int s = m & 4095;
        float4 st;
        st.x = acc[i][0]; st.y = acc[i][1]; st.z = acc[i][2]; st.w = acc[i][3];
        *reinterpret_cast<float4*>(
            &Oh[(((size_t)(b * H_ + h)) * S_ + s) * DK_ + tx * 4]) = st;
    }
}

// ---------------------------------------------------------------------------
// Flash attention, fp32, BQ=64, BK=64, DK=64. Grid: (S/64, B*H). 256 threads.
// Online softmax; mask read directly from gmem (int4 coalesced, L1 cached).
// ---------------------------------------------------------------------------
#define QS_STRIDE 64
#define KS_STRIDE 65
#define VS_STRIDE 64
#define PS_STRIDE 65
#define FLASH_SMEM_FLOATS (64*QS_STRIDE + 64*KS_STRIDE + 64*VS_STRIDE + 64*PS_STRIDE)
#define FLASH_SMEM_BYTES  (FLASH_SMEM_FLOATS * 4)

__global__ void flash_kernel(const int* __restrict__ mask)
{
    extern __shared__ float sm[];
    float* Qs = sm;                         // [64][64]
    float* Ks = Qs + 64 * QS_STRIDE;        // [64][65]
    float* Vs = Ks + 64 * KS_STRIDE;        // [64][64]
    float* Ps = Vs + 64 * VS_STRIDE;        // [64][65]

    const int tid = threadIdx.x;
    const int tx = tid & 15;
    const int ty = tid >> 4;
    const int bh = blockIdx.y;              // b*8 + h
    const int b  = bh >> 3;
    const int q0 = blockIdx.x * 64;

    const float* Qp = g_qh + ((size_t)bh * S_ + q0) * DK_;
    const float* Kp = g_kh + (size_t)bh * S_ * DK_;
    const float* Vp = g_vh + (size_t)bh * S_ * DK_;
    const int*   Mp = mask + ((size_t)b * S_ + q0) * S_;

    // Load Q tile (64x64)
    {
        const int r = tid >> 4;
        const int c = (tid & 15) * 4;
#pragma unroll
        for (int rr = 0; rr < 64; rr += 16) {
            float4 v = *reinterpret_cast<const float4*>(
                &Qp[(size_t)(rr + r) * DK_ + c]);
            Qs[(rr + r) * QS_STRIDE + c + 0] = v.x;
            Qs[(rr + r) * QS_STRIDE + c + 1] = v.y;
            Qs[(rr + r) * QS_STRIDE + c + 2] = v.z;
            Qs[(rr + r) * QS_STRIDE + c + 3] = v.w;
        }
    }

    float m_i[4], l_i[4], Ow[4][4];
#pragma unroll
    for (int i = 0; i < 4; i++) {
        m_i[i] = -INFINITY;
        l_i[i] = 0.f;
#pragma unroll
        for (int j = 0; j < 4; j++) Ow[i][j] = 0.f;
    }

    for (int k0 = 0; k0 < S_; k0 += 64) {
        __syncthreads();   // previous PV finished before overwriting K/V/P
        // Load K and V tiles (64x64 each)
        {
            const int r = tid >> 4;
            const int c = (tid & 15) * 4;
#pragma unroll
            for (int rr = 0; rr < 64; rr += 16) {
                const int row = rr + r;
                float4 kv = *reinterpret_cast<const float4*>(
                    &Kp[(size_t)(k0 + row) * DK_ + c]);
                Ks[row * KS_STRIDE + c + 0] = kv.x;
                Ks[row * KS_STRIDE + c + 1] = kv.y;
                Ks[row * KS_STRIDE + c + 2] = kv.z;
                Ks[row * KS_STRIDE + c + 3] = kv.w;
                float4 vv = *reinterpret_cast<const float4*>(
                    &Vp[(size_t)(k0 + row) * DK_ + c]);
                *reinterpret_cast<float4*>(&Vs[row * VS_STRIDE + c]) = vv;
            }
        }
        __syncthreads();

        // S = Q @ K^T for this tile (4x4 per thread)
        float acc[4][4];
#pragma unroll
        for (int i = 0; i < 4; i++)
#pragma unroll
            for (int j = 0; j < 4; j++) acc[i][j] = 0.f;

#pragma unroll 8
        for (int d = 0; d < 64; d++) {
            float a0 = Qs[(ty * 4 + 0) * QS_STRIDE + d];
            float a1 = Qs[(ty * 4 + 1) * QS_STRIDE + d];
            float a2 = Qs[(ty * 4 + 2) * QS_STRIDE + d];
            float a3 = Qs[(ty * 4 + 3) * QS_STRIDE + d];
            float b0 = Ks[(tx * 4 + 0) * KS_STRIDE + d];
            float b1 = Ks[(tx * 4 + 1) * KS_STRIDE + d];
            float b2 = Ks[(tx * 4 + 2) * KS_STRIDE + d];
            float b3 = Ks[(tx * 4 + 3) * KS_STRIDE + d];
            acc[0][0] += a0 * b0; acc[0][1] += a0 * b1; acc[0][2] += a0 * b2; acc[0][3] += a0 * b3;
            acc[1][0] += a1 * b0; acc[1][1] += a1 * b1; acc[1][2] += a1 * b2; acc[1][3] += a1 * b3;
            acc[2][0] += a2 * b0; acc[2][1] += a2 * b1; acc[2][2] += a2 * b2; acc[2][3] += a2 * b3;
            acc[3][0] += a3 * b0; acc[3][1] += a3 * b1; acc[3][2] += a3 * b2; acc[3][3] += a3 * b3;
        }

        // Mask + scale + tile row max (reduce over the 16 tx lanes)
        const float NEG = -1e9f;
        float mt[4];
#pragma unroll
        for (int i = 0; i < 4; i++) {
            const int4 mv = *reinterpret_cast<const int4*>(
                &Mp[(size_t)(ty * 4 + i) * S_ + k0 + tx * 4]);
            acc[i][0] = (mv.x != 0) ? acc[i][0] * 0.125f : NEG;
            acc[i][1] = (mv.y != 0) ? acc[i][1] * 0.125f : NEG;
            acc[i][2] = (mv.z != 0) ? acc[i][2] * 0.125f : NEG;
            acc[i][3] = (mv.w != 0) ? acc[i][3] * 0.125f : NEG;
            float v = fmaxf(fmaxf(acc[i][0], acc[i][1]), fmaxf(acc[i][2], acc[i][3]));
#pragma unroll
            for (int off = 8; off >= 1; off >>= 1)
                v = fmaxf(v, __shfl_xor_sync(0xffffffffu, v, off));
            mt[i] = v;
        }

        // Online softmax update, write P tile
#pragma unroll
        for (int i = 0; i < 4; i++) {
            const float mnew  = fmaxf(m_i[i], mt[i]);
            const float alpha = __expf(m_i[i] - mnew);
            m_i[i] = mnew;
            float rs = 0.f;
#pragma unroll
            for (int j = 0; j < 4; j++) {
                const float p = __expf(acc[i][j] - mnew);
                Ps[(ty * 4 + i) * PS_STRIDE + tx * 4 + j] = p;
                rs += p;
            }
#pragma unroll
            for (int off = 8; off >= 1; off >>= 1)
                rs += __shfl_xor_sync(0xffffffffu, rs, off);
            l_i[i] = l_i[i] * alpha + rs;
#pragma unroll
            for (int j = 0; j < 4; j++) Ow[i][j] *= alpha;
        }
        __syncthreads();

        // O += P @ V
#pragma unroll 8
        for (int kc = 0; kc < 64; kc++) {
            float p0 = Ps[(ty * 4 + 0) * PS_STRIDE + kc];
            float p1 = Ps[(ty * 4 + 1) * PS_STRIDE + kc];
            float p2 = Ps[(ty * 4 + 2) * PS_STRIDE + kc];
            float p3 = Ps[(ty * 4 + 3) * PS_STRIDE + kc];
            float4 v4 = *reinterpret_cast<const float4*>(&Vs[kc * VS_STRIDE + tx * 4]);
            Ow[0][0] += p0 * v4.x; Ow[0][1] += p0 * v4.y; Ow[0][2] += p0 * v4.z; Ow[0][3] += p0 * v4.w;
            Ow[1][0] += p1 * v4.x; Ow[1][1] += p1 * v4.y; Ow[1][2] += p1 * v4.z; Ow[1][3] += p1 * v4.w;
            Ow[2][0] += p2 * v4.x; Ow[2][1] += p2 * v4.y; Ow[2][2] += p2 * v4.z; Ow[2][3] += p2 * v4.w;
            Ow[3][0] += p3 * v4.x; Ow[3][1] += p3 * v4.y; Ow[3][2] += p3 * v4.z; Ow[3][3] += p3 * v4.w;
        }
    }

    // Epilogue: normalize and store
#pragma unroll
    for (int i = 0; i < 4; i++) {
        const float inv = 1.f / l_i[i];
        float4 o;
        o.x = Ow[i][0] * inv; o.y = Ow[i][1] * inv;
        o.z = Ow[i][2] * inv; o.w = Ow[i][3] * inv;
        *reinterpret_cast<float4*>(
            &g_oh[((size_t)bh * S_ + q0 + ty * 4 + i) * DK_ + tx * 4]) = o;
    }
}

// ---------------------------------------------------------------------------
// Output projection: concat(heads) @ w_o -> out [B,S,D]
// A read permuted from head layout; same tiling as proj_qkv.
// ---------------------------------------------------------------------------
__global__ void out_proj_kernel(const float* __restrict__ W,
                                float* __restrict__ Y)
{
    __shared__ float As[64][33];
    __shared__ float Bs[32][68];

    const int tid = threadIdx.x;
    const int tx = tid & 15;
    const int ty = tid >> 4;
    const int m0 = blockIdx.x * 64;
    const int n0 = blockIdx.y * 64;

    float acc[4][4];
#pragma unroll
    for (int i = 0; i < 4; i++)
#pragma unroll
        for (int j = 0; j < 4; j++) acc[i][j] = 0.f;

    for (int k0 = 0; k0 < 512; k0 += 32) {
        // Load A tile 64x32 from head-layout O
        {
            const int r = tid >> 3;
            const int c = (tid & 7) * 4;
#pragma unroll
            for (int rr = 0; rr < 64; rr += 32) {
                const int m = m0 + r + rr;
                const int b = m >> 12;
                const int s = m & 4095;
                const int kg = k0 + c;        // c..c+3 stay within one head
                const int h  = kg >> 6;
                const int dk = kg & 63;
                float4 v = *reinterpret_cast<const float4*>(
                    &g_oh[(((size_t)(b * H_ + h)) * S_ + s) * DK_ + dk]);
                As[r + rr][c + 0] = v.x;
                As[r + rr][c + 1] = v.y;
                As[r + rr][c + 2] = v.z;
                As[r + rr][c + 3] = v.w;
            }
        }
        // Load B tile 32x64
        {
            const int r = tid >> 4;
            const int c = (tid & 15) * 4;
#pragma unroll
            for (int rr = 0; rr < 32; rr += 16) {
                float4 v = *reinterpret_cast<const float4*>(
                    &W[(size_t)(k0 + r + rr) * 512 + n0 + c]);
                *reinterpret_cast<float4*>(&Bs[r + rr][c]) = v;
            }
        }
        __syncthreads();

#pragma unroll 8
        for (int kk = 0; kk < 32; kk++) {
            float a0 = As[ty * 4 + 0][kk];
            float a1 = As[ty * 4 + 1][kk];
            float a2 = As[ty * 4 + 2][kk];
            float a3 = As[ty * 4 + 3][kk];
            float4 b4 = *reinterpret_cast<const float4*>(&Bs[kk][tx * 4]);
            acc[0][0] += a0 * b4.x; acc[0][1] += a0 * b4.y; acc[0][2] += a0 * b4.z; acc[0][3] += a0 * b4.w;
            acc[1][0] += a1 * b4.x; acc[1][1] += a1 * b4.y; acc[1][2] += a1 * b4.z; acc[1][3] += a1 * b4.w;
            acc[2][0] += a2 * b4.x; acc[2][1] += a2 * b4.y; acc[2][2] += a2 * b4.z; acc[2][3] += a2 * b4.w;
            acc[3][0] += a3 * b4.x; acc[3][1] += a3 * b4.y; acc[3][2] += a3 * b4.z; acc[3][3] += a3 * b4.w;
        }
        __syncthreads();
    }

#pragma unroll
    for (int i = 0; i < 4; i++) {
        const int m = m0 + ty * 4 + i;
        float4 st;
        st.x = acc[i][0]; st.y = acc[i][1]; st.z = acc[i][2]; st.w = acc[i][3];
        *reinterpret_cast<float4*>(&Y[(size_t)m * 512 + n0 + tx * 4]) = st;
    }
}

// ---------------------------------------------------------------------------
extern "C" void kernel_launch(void* const* d_in, const int* in_sizes, int n_in,
                              void* d_out, int out_size)
{
    const float* q    = (const float*)d_in[0];
    const float* k    = (const float*)d_in[1];
    const float* v    = (const float*)d_in[2];
    const int*   mask = (const int*)d_in[3];
    const float* w_q  = (const float*)d_in[4];
    const float* w_k  = (const float*)d_in[5];
    const float* w_v  = (const float*)d_in[6];
    const float* w_o  = (const float*)d_in[7];
    float* out = (float*)d_out;

    cudaFuncSetAttribute(flash_kernel,
                         cudaFuncAttributeMaxDynamicSharedMemorySize,
                         FLASH_SMEM_BYTES);

    dim3 gproj(128, 8);
    dim3 tproj(256);
    proj_qkv_kernel<<<gproj, tproj>>>(q, w_q, 0);
    proj_qkv_kernel<<<gproj, tproj>>>(k, w_k, 1);
    proj_qkv_kernel<<<gproj, tproj>>>(v, w_v, 2);

    dim3 gflash(S_ / 64, B_ * H_);
    flash_kernel<<<gflash, 256, FLASH_SMEM_BYTES>>>(mask);

    out_proj_kernel<<<gproj, tproj>>>(w_o, out);
}

// round 4
// speedup vs baseline: 1.5190x; 1.5190x over previous
#include <cuda_runtime.h>
#include <cuda_bf16.h>
#include <cstdint>

// Problem constants
#define B_   2
#define S_   4096
#define D_   512
#define H_   8
#define DK_  64
#define BHS  (B_*H_*S_*DK_)

// Scratch (head layout [b][h][s][dk])
__device__ float g_qh[BHS];
__device__ float g_kh[BHS];
__device__ float g_vh[BHS];
__device__ float g_oh[BHS];

// ---------------------------------------------------------------------------
// tf32 helpers
// ---------------------------------------------------------------------------
__device__ __forceinline__ float tf32_rna(float x) {
    uint32_t u;
    asm("cvt.rna.tf32.f32 %0, %1;" : "=r"(u) : "f"(x));
    return __uint_as_float(u);
}

__device__ __forceinline__ void mma8(float* d,
                                     uint32_t a0, uint32_t a1, uint32_t a2, uint32_t a3,
                                     uint32_t b0, uint32_t b1) {
    asm volatile(
        "mma.sync.aligned.m16n8k8.row.col.f32.tf32.tf32.f32 "
        "{%0,%1,%2,%3}, {%4,%5,%6,%7}, {%8,%9}, {%0,%1,%2,%3};"
        : "+f"(d[0]), "+f"(d[1]), "+f"(d[2]), "+f"(d[3])
        : "r"(a0), "r"(a1), "r"(a2), "r"(a3), "r"(b0), "r"(b1));
}

// ---------------------------------------------------------------------------
// QKV projection: X[8192,512] @ W[512,512] -> head layout (fp32 FFMA, unchanged)
// ---------------------------------------------------------------------------
__global__ void proj_qkv_kernel(const float* __restrict__ X,
                                const float* __restrict__ W,
                                int which)
{
    __shared__ float As[64][33];
    __shared__ float Bs[32][68];

    const int tid = threadIdx.x;
    const int tx = tid & 15;
    const int ty = tid >> 4;
    const int m0 = blockIdx.x * 64;
    const int n0 = blockIdx.y * 64;

    float acc[4][4];
#pragma unroll
    for (int i = 0; i < 4; i++)
#pragma unroll
        for (int j = 0; j < 4; j++) acc[i][j] = 0.f;

    for (int k0 = 0; k0 < 512; k0 += 32) {
        {
            const int r = tid >> 3;
            const int c = (tid & 7) * 4;
#pragma unroll
            for (int rr = 0; rr < 64; rr += 32) {
                float4 v = *reinterpret_cast<const float4*>(
                    &X[(size_t)(m0 + r + rr) * 512 + k0 + c]);
                As[r + rr][c + 0] = v.x;
                As[r + rr][c + 1] = v.y;
                As[r + rr][c + 2] = v.z;
                As[r + rr][c + 3] = v.w;
            }
        }
        {
            const int r = tid >> 4;
            const int c = (tid & 15) * 4;
#pragma unroll
            for (int rr = 0; rr < 32; rr += 16) {
                float4 v = *reinterpret_cast<const float4*>(
                    &W[(size_t)(k0 + r + rr) * 512 + n0 + c]);
                *reinterpret_cast<float4*>(&Bs[r + rr][c]) = v;
            }
        }
        __syncthreads();

#pragma unroll 8
        for (int kk = 0; kk < 32; kk++) {
            float a0 = As[ty * 4 + 0][kk];
            float a1 = As[ty * 4 + 1][kk];
            float a2 = As[ty * 4 + 2][kk];
            float a3 = As[ty * 4 + 3][kk];
            float4 b4 = *reinterpret_cast<const float4*>(&Bs[kk][tx * 4]);
            acc[0][0] += a0 * b4.x; acc[0][1] += a0 * b4.y; acc[0][2] += a0 * b4.z; acc[0][3] += a0 * b4.w;
            acc[1][0] += a1 * b4.x; acc[1][1] += a1 * b4.y; acc[1][2] += a1 * b4.z; acc[1][3] += a1 * b4.w;
            acc[2][0] += a2 * b4.x; acc[2][1] += a2 * b4.y; acc[2][2] += a2 * b4.z; acc[2][3] += a2 * b4.w;
            acc[3][0] += a3 * b4.x; acc[3][1] += a3 * b4.y; acc[3][2] += a3 * b4.z; acc[3][3] += a3 * b4.w;
        }
        __syncthreads();
    }

    float* Oh = (which == 0) ? g_qh : (which == 1) ? g_kh : g_vh;
    const int h = n0 >> 6;
#pragma unroll
    for (int i = 0; i < 4; i++) {
        const int m = m0 + ty * 4 + i;
        const int b = m >> 12;
        const int s = m & 4095;
        float4 st;
        st.x = acc[i][0]; st.y = acc[i][1]; st.z = acc[i][2]; st.w = acc[i][3];
        *reinterpret_cast<float4*>(
            &Oh[(((size_t)(b * H_ + h)) * S_ + s) * DK_ + tx * 4]) = st;
    }
}

// ---------------------------------------------------------------------------
// Flash attention with tf32 mma.sync. BQ=128, BK=64, DK=64. 256 thr (8 warps).
// Each warp owns 16 full-width q-rows. QK^T uses 3xTF32 (hi/lo split);
// PV uses single tf32 (P in [0,1], V quantization ~3e-4).
// ---------------------------------------------------------------------------
#define KH_STRIDE 68   // K hi/lo: bank = g*4+tig  (conflict-free B-frag loads)
#define VS_STR    72   // V:       bank = tig*8+g  (conflict-free B-frag loads)
#define PS_STR    76   // P:       bank = g*12+tig (conflict-free A-frag loads)

#define SM_KHI 0
#define SM_KLO (64*KH_STRIDE)
#define SM_VS  (2*64*KH_STRIDE)
#define SM_PS  (SM_VS + 64*VS_STR)
#define FL_SMEM_FLOATS (SM_PS + 128*PS_STR)
#define FL_SMEM_BYTES  (FL_SMEM_FLOATS * 4)

__global__ __launch_bounds__(256, 1) void flash_mma_kernel(const int* __restrict__ mask)
{
    extern __shared__ float sm[];
    float* Khi = sm + SM_KHI;
    float* Klo = sm + SM_KLO;
    float* Vs  = sm + SM_VS;
    float* Ps  = sm + SM_PS;

    const int tid  = threadIdx.x;
    const int wid  = tid >> 5;
    const int lane = tid & 31;
    const int g    = lane >> 2;   // groupID
    const int tig  = lane & 3;    // thread-in-group
    const int bh   = blockIdx.y;  // b*8 + h
    const int b    = bh >> 3;
    const int q0   = blockIdx.x * 128;

    const int r0 = wid * 16 + g;  // block-local q row (pair row is r0+8)

    const float* Kp = g_kh + (size_t)bh * S_ * DK_;
    const float* Vp = g_vh + (size_t)bh * S_ * DK_;

    // --- Q fragments (hi/lo) resident in registers, loaded once ---
    uint32_t qhi[8][4], qlo[8][4];
    {
        const float* Q0 = g_qh + ((size_t)bh * S_ + q0 + r0) * DK_;
        const float* Q1 = Q0 + 8 * DK_;
#pragma unroll
        for (int ks = 0; ks < 8; ks++) {
            float x0 = Q0[ks*8 + tig],     x1 = Q1[ks*8 + tig];
            float x2 = Q0[ks*8 + tig + 4], x3 = Q1[ks*8 + tig + 4];
            float h;
            h = tf32_rna(x0); qhi[ks][0] = __float_as_uint(h); qlo[ks][0] = __float_as_uint(tf32_rna(x0 - h));
            h = tf32_rna(x1); qhi[ks][1] = __float_as_uint(h); qlo[ks][1] = __float_as_uint(tf32_rna(x1 - h));
            h = tf32_rna(x2); qhi[ks][2] = __float_as_uint(h); qlo[ks][2] = __float_as_uint(tf32_rna(x2 - h));
            h = tf32_rna(x3); qhi[ks][3] = __float_as_uint(h); qlo[ks][3] = __float_as_uint(tf32_rna(x3 - h));
        }
    }

    const int* Mp0 = mask + ((size_t)b * S_ + q0 + r0) * S_;
    const int* Mp1 = Mp0 + 8 * S_;

    float of[8][4];
#pragma unroll
    for (int nf = 0; nf < 8; nf++) { of[nf][0]=of[nf][1]=of[nf][2]=of[nf][3]=0.f; }
    float m0 = -INFINITY, m1 = -INFINITY, l0 = 0.f, l1 = 0.f;

    const int lr = tid >> 4;         // loader row 0..15
    const int lc = (tid & 15) * 4;   // loader col 0..60

    for (int k0 = 0; k0 < S_; k0 += 64) {
        __syncthreads();   // previous PV done reading Vs/Ps; QK done with Khi/Klo

        // Load K (hi/lo split) + V (tf32-rounded) tiles
#pragma unroll
        for (int rr = 0; rr < 64; rr += 16) {
            const int row = rr + lr;
            float4 kv = *reinterpret_cast<const float4*>(&Kp[(size_t)(k0 + row) * DK_ + lc]);
            float h0 = tf32_rna(kv.x), h1 = tf32_rna(kv.y), h2 = tf32_rna(kv.z), h3 = tf32_rna(kv.w);
            float4 hv = {h0, h1, h2, h3};
            float4 lv = {tf32_rna(kv.x - h0), tf32_rna(kv.y - h1),
                         tf32_rna(kv.z - h2), tf32_rna(kv.w - h3)};
            *reinterpret_cast<float4*>(&Khi[row * KH_STRIDE + lc]) = hv;
            *reinterpret_cast<float4*>(&Klo[row * KH_STRIDE + lc]) = lv;
            float4 vv = *reinterpret_cast<const float4*>(&Vp[(size_t)(k0 + row) * DK_ + lc]);
            float4 vq = {tf32_rna(vv.x), tf32_rna(vv.y), tf32_rna(vv.z), tf32_rna(vv.w)};
            *reinterpret_cast<float4*>(&Vs[row * VS_STR + lc]) = vq;
        }
        __syncthreads();

        // ---- S = Q @ K^T  (3xTF32) ----
        float sf[8][4];
#pragma unroll
        for (int nf = 0; nf < 8; nf++) { sf[nf][0]=sf[nf][1]=sf[nf][2]=sf[nf][3]=0.f; }

#pragma unroll
        for (int ks = 0; ks < 8; ks++) {
            const int kcol = ks * 8 + tig;
#pragma unroll
            for (int nf = 0; nf < 8; nf++) {
                const int krow = nf * 8 + g;
                uint32_t bh0 = __float_as_uint(Khi[krow * KH_STRIDE + kcol]);
                uint32_t bh1 = __float_as_uint(Khi[krow * KH_STRIDE + kcol + 4]);
                uint32_t bl0 = __float_as_uint(Klo[krow * KH_STRIDE + kcol]);
                uint32_t bl1 = __float_as_uint(Klo[krow * KH_STRIDE + kcol + 4]);
                mma8(sf[nf], qhi[ks][0], qhi[ks][1], qhi[ks][2], qhi[ks][3], bh0, bh1);
                mma8(sf[nf], qlo[ks][0], qlo[ks][1], qlo[ks][2], qlo[ks][3], bh0, bh1);
                mma8(sf[nf], qhi[ks][0], qhi[ks][1], qhi[ks][2], qhi[ks][3], bl0, bl1);
            }
        }

        // ---- mask + scale + online softmax ----
        const float NEG = -1e9f;
        float mt0 = -INFINITY, mt1 = -INFINITY;
#pragma unroll
        for (int nf = 0; nf < 8; nf++) {
            const int col = k0 + nf * 8 + 2 * tig;
            int2 ma = *reinterpret_cast<const int2*>(&Mp0[col]);
            int2 mb = *reinterpret_cast<const int2*>(&Mp1[col]);
            sf[nf][0] = ma.x ? sf[nf][0] * 0.125f : NEG;
            sf[nf][1] = ma.y ? sf[nf][1] * 0.125f : NEG;
            sf[nf][2] = mb.x ? sf[nf][2] * 0.125f : NEG;
            sf[nf][3] = mb.y ? sf[nf][3] * 0.125f : NEG;
            mt0 = fmaxf(mt0, fmaxf(sf[nf][0], sf[nf][1]));
            mt1 = fmaxf(mt1, fmaxf(sf[nf][2], sf[nf][3]));
        }
        mt0 = fmaxf(mt0, __shfl_xor_sync(0xffffffffu, mt0, 1));
        mt0 = fmaxf(mt0, __shfl_xor_sync(0xffffffffu, mt0, 2));
        mt1 = fmaxf(mt1, __shfl_xor_sync(0xffffffffu, mt1, 1));
        mt1 = fmaxf(mt1, __shfl_xor_sync(0xffffffffu, mt1, 2));

        const float mn0 = fmaxf(m0, mt0), mn1 = fmaxf(m1, mt1);
        const float al0 = __expf(m0 - mn0), al1 = __expf(m1 - mn1);
        m0 = mn0; m1 = mn1;

        float rs0 = 0.f, rs1 = 0.f;
        float* P0 = &Ps[r0 * PS_STR];
        float* P1 = &Ps[(r0 + 8) * PS_STR];
#pragma unroll
        for (int nf = 0; nf < 8; nf++) {
            float p0 = __expf(sf[nf][0] - m0), p1 = __expf(sf[nf][1] - m0);
            float p2 = __expf(sf[nf][2] - m1), p3 = __expf(sf[nf][3] - m1);
            rs0 += p0 + p1; rs1 += p2 + p3;
            float2 q01 = {tf32_rna(p0), tf32_rna(p1)};
            float2 q23 = {tf32_rna(p2), tf32_rna(p3)};
            *reinterpret_cast<float2*>(&P0[nf * 8 + 2 * tig]) = q01;
            *reinterpret_cast<float2*>(&P1[nf * 8 + 2 * tig]) = q23;
        }
        rs0 += __shfl_xor_sync(0xffffffffu, rs0, 1);
        rs0 += __shfl_xor_sync(0xffffffffu, rs0, 2);
        rs1 += __shfl_xor_sync(0xffffffffu, rs1, 1);
        rs1 += __shfl_xor_sync(0xffffffffu, rs1, 2);
        l0 = l0 * al0 + rs0;
        l1 = l1 * al1 + rs1;
#pragma unroll
        for (int nf = 0; nf < 8; nf++) {
            of[nf][0] *= al0; of[nf][1] *= al0;
            of[nf][2] *= al1; of[nf][3] *= al1;
        }
        __syncthreads();   // Ps visible to all lanes before PV

        // ---- O += P @ V  (single tf32) ----
#pragma unroll
        for (int ks = 0; ks < 8; ks++) {
            uint32_t a0 = __float_as_uint(Ps[r0 * PS_STR + ks * 8 + tig]);
            uint32_t a1 = __float_as_uint(Ps[(r0 + 8) * PS_STR + ks * 8 + tig]);
            uint32_t a2 = __float_as_uint(Ps[r0 * PS_STR + ks * 8 + tig + 4]);
            uint32_t a3 = __float_as_uint(Ps[(r0 + 8) * PS_STR + ks * 8 + tig + 4]);
#pragma unroll
            for (int nf = 0; nf < 8; nf++) {
                uint32_t b0 = __float_as_uint(Vs[(ks * 8 + tig) * VS_STR + nf * 8 + g]);
                uint32_t b1 = __float_as_uint(Vs[(ks * 8 + tig + 4) * VS_STR + nf * 8 + g]);
                mma8(of[nf], a0, a1, a2, a3, b0, b1);
            }
        }
    }

    // ---- epilogue: normalize + store ----
    const float inv0 = 1.f / l0, inv1 = 1.f / l1;
    float* O0 = g_oh + ((size_t)bh * S_ + q0 + r0) * DK_;
    float* O1 = O0 + 8 * DK_;
#pragma unroll
    for (int nf = 0; nf < 8; nf++) {
        float2 o01 = {of[nf][0] * inv0, of[nf][1] * inv0};
        float2 o23 = {of[nf][2] * inv1, of[nf][3] * inv1};
        *reinterpret_cast<float2*>(&O0[nf * 8 + 2 * tig]) = o01;
        *reinterpret_cast<float2*>(&O1[nf * 8 + 2 * tig]) = o23;
    }
}

// ---------------------------------------------------------------------------
// Output projection (fp32 FFMA, unchanged)
// ---------------------------------------------------------------------------
__global__ void out_proj_kernel(const float* __restrict__ W,
                                float* __restrict__ Y)
{
    __shared__ float As[64][33];
    __shared__ float Bs[32][68];

    const int tid = threadIdx.x;
    const int tx = tid & 15;
    const int ty = tid >> 4;
    const int m0 = blockIdx.x * 64;
    const int n0 = blockIdx.y * 64;

    float acc[4][4];
#pragma unroll
    for (int i = 0; i < 4; i++)
#pragma unroll
        for (int j = 0; j < 4; j++) acc[i][j] = 0.f;

    for (int k0 = 0; k0 < 512; k0 += 32) {
        {
            const int r = tid >> 3;
            const int c = (tid & 7) * 4;
#pragma unroll
            for (int rr = 0; rr < 64; rr += 32) {
                const int m = m0 + r + rr;
                const int b = m >> 12;
                const int s = m & 4095;
                const int kg = k0 + c;
                const int h  = kg >> 6;
                const int dk = kg & 63;
                float4 v = *reinterpret_cast<const float4*>(
                    &g_oh[(((size_t)(b * H_ + h)) * S_ + s) * DK_ + dk]);
                As[r + rr][c + 0] = v.x;
                As[r + rr][c + 1] = v.y;
                As[r + rr][c + 2] = v.z;
                As[r + rr][c + 3] = v.w;
            }
        }
        {
            const int r = tid >> 4;
            const int c = (tid & 15) * 4;
#pragma unroll
            for (int rr = 0; rr < 32; rr += 16) {
                float4 v = *reinterpret_cast<const float4*>(
                    &W[(size_t)(k0 + r + rr) * 512 + n0 + c]);
                *reinterpret_cast<float4*>(&Bs[r + rr][c]) = v;
            }
        }
        __syncthreads();

#pragma unroll 8
        for (int kk = 0; kk < 32; kk++) {
            float a0 = As[ty * 4 + 0][kk];
            float a1 = As[ty * 4 + 1][kk];
            float a2 = As[ty * 4 + 2][kk];
            float a3 = As[ty * 4 + 3][kk];
            float4 b4 = *reinterpret_cast<const float4*>(&Bs[kk][tx * 4]);
            acc[0][0] += a0 * b4.x; acc[0][1] += a0 * b4.y; acc[0][2] += a0 * b4.z; acc[0][3] += a0 * b4.w;
            acc[1][0] += a1 * b4.x; acc[1][1] += a1 * b4.y; acc[1][2] += a1 * b4.z; acc[1][3] += a1 * b4.w;
            acc[2][0] += a2 * b4.x; acc[2][1] += a2 * b4.y; acc[2][2] += a2 * b4.z; acc[2][3] += a2 * b4.w;
            acc[3][0] += a3 * b4.x; acc[3][1] += a3 * b4.y; acc[3][2] += a3 * b4.z; acc[3][3] += a3 * b4.w;
        }
        __syncthreads();
    }

#pragma unroll
    for (int i = 0; i < 4; i++) {
        const int m = m0 + ty * 4 + i;
        float4 st;
        st.x = acc[i][0]; st.y = acc[i][1]; st.z = acc[i][2]; st.w = acc[i][3];
        *reinterpret_cast<float4*>(&Y[(size_t)m * 512 + n0 + tx * 4]) = st;
    }
}

// ---------------------------------------------------------------------------
extern "C" void kernel_launch(void* const* d_in, const int* in_sizes, int n_in,
                              void* d_out, int out_size)
{
    const float* q    = (const float*)d_in[0];
    const float* k    = (const float*)d_in[1];
    const float* v    = (const float*)d_in[2];
    const int*   mask = (const int*)d_in[3];
    const float* w_q  = (const float*)d_in[4];
    const float* w_k  = (const float*)d_in[5];
    const float* w_v  = (const float*)d_in[6];
    const float* w_o  = (const float*)d_in[7];
    float* out = (float*)d_out;

    cudaFuncSetAttribute(flash_mma_kernel,
                         cudaFuncAttributeMaxDynamicSharedMemorySize,
                         FL_SMEM_BYTES);

    dim3 gproj(128, 8);
    dim3 tproj(256);
    proj_qkv_kernel<<<gproj, tproj>>>(q, w_q, 0);
    proj_qkv_kernel<<<gproj, tproj>>>(k, w_k, 1);
    proj_qkv_kernel<<<gproj, tproj>>>(v, w_v, 2);

    dim3 gflash(S_ / 128, B_ * H_);
    flash_mma_kernel<<<gflash, 256, FL_SMEM_BYTES>>>(mask);

    out_proj_kernel<<<gproj, tproj>>>(w_o, out);
}

// round 6
// speedup vs baseline: 1.6519x; 1.0875x over previous
#include <cuda_runtime.h>
#include <cuda_bf16.h>
#include <cstdint>

// Problem constants
#define B_   2
#define S_   4096
#define D_   512
#define H_   8
#define DK_  64
#define BHS  (B_*H_*S_*DK_)

// Scratch (head layout [b][h][s][dk])
__device__ float g_qh[BHS];
__device__ float g_kh[BHS];
__device__ float g_vh[BHS];
__device__ float g_oh[BHS];

// ---------------------------------------------------------------------------
// tf32 / cp.async helpers
// ---------------------------------------------------------------------------
__device__ __forceinline__ float tf32_rna(float x) {
    uint32_t u;
    asm("cvt.rna.tf32.f32 %0, %1;" : "=r"(u) : "f"(x));
    return __uint_as_float(u);
}

__device__ __forceinline__ void mma8(float* d,
                                     uint32_t a0, uint32_t a1, uint32_t a2, uint32_t a3,
                                     uint32_t b0, uint32_t b1) {
    asm volatile(
        "mma.sync.aligned.m16n8k8.row.col.f32.tf32.tf32.f32 "
        "{%0,%1,%2,%3}, {%4,%5,%6,%7}, {%8,%9}, {%0,%1,%2,%3};"
        : "+f"(d[0]), "+f"(d[1]), "+f"(d[2]), "+f"(d[3])
        : "r"(a0), "r"(a1), "r"(a2), "r"(a3), "r"(b0), "r"(b1));
}

__device__ __forceinline__ void cpa16(uint32_t s, const void* g) {
    asm volatile("cp.async.cg.shared.global [%0], [%1], 16;"
                 :: "r"(s), "l"(g) : "memory");
}
#define CPA_COMMIT()  asm volatile("cp.async.commit_group;" ::: "memory")
#define CPA_WAIT_1()  asm volatile("cp.async.wait_group 1;" ::: "memory")
#define CPA_WAIT_0()  asm volatile("cp.async.wait_group 0;" ::: "memory")

// ---------------------------------------------------------------------------
// QKV projection: X[8192,512] @ W[512,512] -> head layout (fp32 FFMA)
// ---------------------------------------------------------------------------
__global__ void proj_qkv_kernel(const float* __restrict__ X,
                                const float* __restrict__ W,
                                int which)
{
    __shared__ float As[64][33];
    __shared__ float Bs[32][68];

    const int tid = threadIdx.x;
    const int tx = tid & 15;
    const int ty = tid >> 4;
    const int m0 = blockIdx.x * 64;
    const int n0 = blockIdx.y * 64;

    float acc[4][4];
#pragma unroll
    for (int i = 0; i < 4; i++)
#pragma unroll
        for (int j = 0; j < 4; j++) acc[i][j] = 0.f;

    for (int k0 = 0; k0 < 512; k0 += 32) {
        {
            const int r = tid >> 3;
            const int c = (tid & 7) * 4;
#pragma unroll
            for (int rr = 0; rr < 64; rr += 32) {
                float4 v = *reinterpret_cast<const float4*>(
                    &X[(size_t)(m0 + r + rr) * 512 + k0 + c]);
                As[r + rr][c + 0] = v.x;
                As[r + rr][c + 1] = v.y;
                As[r + rr][c + 2] = v.z;
                As[r + rr][c + 3] = v.w;
            }
        }
        {
            const int r = tid >> 4;
            const int c = (tid & 15) * 4;
#pragma unroll
            for (int rr = 0; rr < 32; rr += 16) {
                float4 v = *reinterpret_cast<const float4*>(
                    &W[(size_t)(k0 + r + rr) * 512 + n0 + c]);
                *reinterpret_cast<float4*>(&Bs[r + rr][c]) = v;
            }
        }
        __syncthreads();

#pragma unroll 8
        for (int kk = 0; kk < 32; kk++) {
            float a0 = As[ty * 4 + 0][kk];
            float a1 = As[ty * 4 + 1][kk];
            float a2 = As[ty * 4 + 2][kk];
            float a3 = As[ty * 4 + 3][kk];
            float4 b4 = *reinterpret_cast<const float4*>(&Bs[kk][tx * 4]);
            acc[0][0] += a0 * b4.x; acc[0][1] += a0 * b4.y; acc[0][2] += a0 * b4.z; acc[0][3] += a0 * b4.w;
            acc[1][0] += a1 * b4.x; acc[1][1] += a1 * b4.y; acc[1][2] += a1 * b4.z; acc[1][3] += a1 * b4.w;
            acc[2][0] += a2 * b4.x; acc[2][1] += a2 * b4.y; acc[2][2] += a2 * b4.z; acc[2][3] += a2 * b4.w;
            acc[3][0] += a3 * b4.x; acc[3][1] += a3 * b4.y; acc[3][2] += a3 * b4.z; acc[3][3] += a3 * b4.w;
        }
        __syncthreads();
    }

    float* Oh = (which == 0) ? g_qh : (which == 1) ? g_kh : g_vh;
    const int h = n0 >> 6;
#pragma unroll
    for (int i = 0; i < 4; i++) {
        const int m = m0 + ty * 4 + i;
        const int b = m >> 12;
        const int s = m & 4095;
        float4 st;
        st.x = acc[i][0]; st.y = acc[i][1]; st.z = acc[i][2]; st.w = acc[i][3];
        *reinterpret_cast<float4*>(
            &Oh[(((size_t)(b * H_ + h)) * S_ + s) * DK_ + tx * 4]) = st;
    }
}

// ---------------------------------------------------------------------------
// Flash attention v2: tf32 mma, cp.async double-buffered K/V, 2-term QK.
// BQ=128, BK=64, DK=64. 256 threads (8 warps), each warp owns 16 q-rows.
// ---------------------------------------------------------------------------
#define KR_STR 68   // raw K: bank = 4g + tig for B-frag loads  -> conflict-free
#define VR_STR 72   // raw V: bank = 8tig + g                   -> conflict-free
#define PS_STR 76   // P:     bank = 12g + tig                  -> conflict-free

#define SM_K   0
#define SM_V   (2*64*KR_STR)
#define SM_P   (SM_V + 2*64*VR_STR)
#define FL_SMEM_FLOATS (SM_P + 128*PS_STR)
#define FL_SMEM_BYTES  (FL_SMEM_FLOATS * 4)
#define NT     (S_/64)

__global__ __launch_bounds__(256, 1) void flash_mma_kernel(const int* __restrict__ mask)
{
    extern __shared__ float sm[];
    float* Kr = sm + SM_K;      // [2][64][KR_STR]
    float* Vr = sm + SM_V;      // [2][64][VR_STR]
    float* Ps = sm + SM_P;      // [128][PS_STR]
    const uint32_t k_u32 = (uint32_t)__cvta_generic_to_shared(Kr);
    const uint32_t v_u32 = (uint32_t)__cvta_generic_to_shared(Vr);

    const int tid  = threadIdx.x;
    const int wid  = tid >> 5;
    const int lane = tid & 31;
    const int g    = lane >> 2;
    const int tig  = lane & 3;
    const int bh   = blockIdx.y;
    const int b    = bh >> 3;
    const int q0   = blockIdx.x * 128;

    const int r0 = wid * 16 + g;

    const float* Kp = g_kh + (size_t)bh * S_ * DK_;
    const float* Vp = g_vh + (size_t)bh * S_ * DK_;

    const int lr = tid >> 4;         // loader row 0..15
    const int lc = (tid & 15) * 4;   // loader col (floats)

    // --- Q fragments (hi/lo) resident in registers ---
    uint32_t qhi[8][4], qlo[8][4];
    {
        const float* Q0 = g_qh + ((size_t)bh * S_ + q0 + r0) * DK_;
        const float* Q1 = Q0 + 8 * DK_;
#pragma unroll
        for (int ks = 0; ks < 8; ks++) {
            float x0 = Q0[ks*8 + tig],     x1 = Q1[ks*8 + tig];
            float x2 = Q0[ks*8 + tig + 4], x3 = Q1[ks*8 + tig + 4];
            float h;
            h = tf32_rna(x0); qhi[ks][0] = __float_as_uint(h); qlo[ks][0] = __float_as_uint(tf32_rna(x0 - h));
            h = tf32_rna(x1); qhi[ks][1] = __float_as_uint(h); qlo[ks][1] = __float_as_uint(tf32_rna(x1 - h));
            h = tf32_rna(x2); qhi[ks][2] = __float_as_uint(h); qlo[ks][2] = __float_as_uint(tf32_rna(x2 - h));
            h = tf32_rna(x3); qhi[ks][3] = __float_as_uint(h); qlo[ks][3] = __float_as_uint(tf32_rna(x3 - h));
        }
    }

    const int* Mp0 = mask + ((size_t)b * S_ + q0 + r0) * S_;
    const int* Mp1 = Mp0 + 8 * S_;

    float of[8][4];
#pragma unroll
    for (int nf = 0; nf < 8; nf++) { of[nf][0]=of[nf][1]=of[nf][2]=of[nf][3]=0.f; }
    float m0 = -INFINITY, m1 = -INFINITY, l0 = 0.f, l1 = 0.f;

    // Prologue: issue tile 0 into buffer 0
    {
        const float* Kg = Kp + (size_t)lr * DK_ + lc;
        const float* Vg = Vp + (size_t)lr * DK_ + lc;
#pragma unroll
        for (int rr = 0; rr < 64; rr += 16) {
            cpa16(k_u32 + (uint32_t)(((rr + lr) * KR_STR + lc) * 4), Kg + (size_t)rr * DK_);
            cpa16(v_u32 + (uint32_t)(((rr + lr) * VR_STR + lc) * 4), Vg + (size_t)rr * DK_);
        }
        CPA_COMMIT();
    }

    for (int t = 0; t < NT; t++) {
        const int buf = t & 1;
        __syncthreads();   // all warps done with buf^1 contents (tile t-1 PV)

        if (t + 1 < NT) {
            const int nb = buf ^ 1;
            const float* Kg = Kp + (size_t)((t + 1) * 64 + lr) * DK_ + lc;
            const float* Vg = Vp + (size_t)((t + 1) * 64 + lr) * DK_ + lc;
#pragma unroll
            for (int rr = 0; rr < 64; rr += 16) {
                cpa16(k_u32 + (uint32_t)(((nb * 64 + rr + lr) * KR_STR + lc) * 4), Kg + (size_t)rr * DK_);
                cpa16(v_u32 + (uint32_t)(((nb * 64 + rr + lr) * VR_STR + lc) * 4), Vg + (size_t)rr * DK_);
            }
            CPA_COMMIT();
            CPA_WAIT_1();   // tile t done, tile t+1 may still fly
        } else {
            CPA_WAIT_0();
        }
        __syncthreads();   // tile-t data (copied by other threads) visible

        const float* Kb = Kr + buf * 64 * KR_STR;
        const float* Vb = Vr + buf * 64 * VR_STR;
        const int k0 = t * 64;

        // Prefetch mask into registers (latency hides under QK MMAs)
        int2 ma[8], mb[8];
#pragma unroll
        for (int nf = 0; nf < 8; nf++) {
            const int col = k0 + nf * 8 + 2 * tig;
            ma[nf] = *reinterpret_cast<const int2*>(&Mp0[col]);
            mb[nf] = *reinterpret_cast<const int2*>(&Mp1[col]);
        }

        // ---- S = Q @ K^T  (2-term: qhi*khi + qlo*khi) ----
        float sf[8][4];
#pragma unroll
        for (int nf = 0; nf < 8; nf++) { sf[nf][0]=sf[nf][1]=sf[nf][2]=sf[nf][3]=0.f; }

#pragma unroll
        for (int ks = 0; ks < 8; ks++) {
            const int kcol = ks * 8 + tig;
#pragma unroll
            for (int nf = 0; nf < 8; nf++) {
                const int krow = nf * 8 + g;
                uint32_t bh0 = __float_as_uint(tf32_rna(Kb[krow * KR_STR + kcol]));
                uint32_t bh1 = __float_as_uint(tf32_rna(Kb[krow * KR_STR + kcol + 4]));
                mma8(sf[nf], qhi[ks][0], qhi[ks][1], qhi[ks][2], qhi[ks][3], bh0, bh1);
                mma8(sf[nf], qlo[ks][0], qlo[ks][1], qlo[ks][2], qlo[ks][3], bh0, bh1);
            }
        }

        // ---- mask + scale + online softmax ----
        const float NEG = -1e9f;
        float mt0 = -INFINITY, mt1 = -INFINITY;
#pragma unroll
        for (int nf = 0; nf < 8; nf++) {
            sf[nf][0] = ma[nf].x ? sf[nf][0] * 0.125f : NEG;
            sf[nf][1] = ma[nf].y ? sf[nf][1] * 0.125f : NEG;
            sf[nf][2] = mb[nf].x ? sf[nf][2] * 0.125f : NEG;
            sf[nf][3] = mb[nf].y ? sf[nf][3] * 0.125f : NEG;
            mt0 = fmaxf(mt0, fmaxf(sf[nf][0], sf[nf][1]));
            mt1 = fmaxf(mt1, fmaxf(sf[nf][2], sf[nf][3]));
        }
        mt0 = fmaxf(mt0, __shfl_xor_sync(0xffffffffu, mt0, 1));
        mt0 = fmaxf(mt0, __shfl_xor_sync(0xffffffffu, mt0, 2));
        mt1 = fmaxf(mt1, __shfl_xor_sync(0xffffffffu, mt1, 1));
        mt1 = fmaxf(mt1, __shfl_xor_sync(0xffffffffu, mt1, 2));

        const float mn0 = fmaxf(m0, mt0), mn1 = fmaxf(m1, mt1);
        const float al0 = __expf(m0 - mn0), al1 = __expf(m1 - mn1);
        m0 = mn0; m1 = mn1;

        float rs0 = 0.f, rs1 = 0.f;
        float* P0 = &Ps[r0 * PS_STR];
        float* P1 = &Ps[(r0 + 8) * PS_STR];
#pragma unroll
        for (int nf = 0; nf < 8; nf++) {
            float p0 = __expf(sf[nf][0] - m0), p1 = __expf(sf[nf][1] - m0);
            float p2 = __expf(sf[nf][2] - m1), p3 = __expf(sf[nf][3] - m1);
            rs0 += p0 + p1; rs1 += p2 + p3;
            float2 q01 = {tf32_rna(p0), tf32_rna(p1)};
            float2 q23 = {tf32_rna(p2), tf32_rna(p3)};
            *reinterpret_cast<float2*>(&P0[nf * 8 + 2 * tig]) = q01;
            *reinterpret_cast<float2*>(&P1[nf * 8 + 2 * tig]) = q23;
        }
        rs0 += __shfl_xor_sync(0xffffffffu, rs0, 1);
        rs0 += __shfl_xor_sync(0xffffffffu, rs0, 2);
        rs1 += __shfl_xor_sync(0xffffffffu, rs1, 1);
        rs1 += __shfl_xor_sync(0xffffffffu, rs1, 2);
        l0 = l0 * al0 + rs0;
        l1 = l1 * al1 + rs1;
#pragma unroll
        for (int nf = 0; nf < 8; nf++) {
            of[nf][0] *= al0; of[nf][1] *= al0;
            of[nf][2] *= al1; of[nf][3] *= al1;
        }
        __syncwarp();   // P rows are warp-private: warp-level sync suffices

        // ---- O += P @ V  (single tf32, V rna'd at use) ----
#pragma unroll
        for (int ks = 0; ks < 8; ks++) {
            uint32_t a0 = __float_as_uint(Ps[r0 * PS_STR + ks * 8 + tig]);
            uint32_t a1 = __float_as_uint(Ps[(r0 + 8) * PS_STR + ks * 8 + tig]);
            uint32_t a2 = __float_as_uint(Ps[r0 * PS_STR + ks * 8 + tig + 4]);
            uint32_t a3 = __float_as_uint(Ps[(r0 + 8) * PS_STR + ks * 8 + tig + 4]);
#pragma unroll
            for (int nf = 0; nf < 8; nf++) {
                uint32_t b0 = __float_as_uint(tf32_rna(Vb[(ks * 8 + tig) * VR_STR + nf * 8 + g]));
                uint32_t b1 = __float_as_uint(tf32_rna(Vb[(ks * 8 + tig + 4) * VR_STR + nf * 8 + g]));
                mma8(of[nf], a0, a1, a2, a3, b0, b1);
            }
        }
    }

    // ---- epilogue: normalize + store ----
    const float inv0 = 1.f / l0, inv1 = 1.f / l1;
    float* O0 = g_oh + ((size_t)bh * S_ + q0 + r0) * DK_;
    float* O1 = O0 + 8 * DK_;
#pragma unroll
    for (int nf = 0; nf < 8; nf++) {
        float2 o01 = {of[nf][0] * inv0, of[nf][1] * inv0};
        float2 o23 = {of[nf][2] * inv1, of[nf][3] * inv1};
        *reinterpret_cast<float2*>(&O0[nf * 8 + 2 * tig]) = o01;
        *reinterpret_cast<float2*>(&O1[nf * 8 + 2 * tig]) = o23;
    }
}

// ---------------------------------------------------------------------------
// Output projection (fp32 FFMA)
// ---------------------------------------------------------------------------
__global__ void out_proj_kernel(const float* __restrict__ W,
                                float* __restrict__ Y)
{
    __shared__ float As[64][33];
    __shared__ float Bs[32][68];

    const int tid = threadIdx.x;
    const int tx = tid & 15;
    const int ty = tid >> 4;
    const int m0 = blockIdx.x * 64;
    const int n0 = blockIdx.y * 64;

    float acc[4][4];
#pragma unroll
    for (int i = 0; i < 4; i++)
#pragma unroll
        for (int j = 0; j < 4; j++) acc[i][j] = 0.f;

    for (int k0 = 0; k0 < 512; k0 += 32) {
        {
            const int r = tid >> 3;
            const int c = (tid & 7) * 4;
#pragma unroll
            for (int rr = 0; rr < 64; rr += 32) {
                const int m = m0 + r + rr;
                const int b = m >> 12;
                const int s = m & 4095;
                const int kg = k0 + c;
                const int h  = kg >> 6;
                const int dk = kg & 63;
                float4 v = *reinterpret_cast<const float4*>(
                    &g_oh[(((size_t)(b * H_ + h)) * S_ + s) * DK_ + dk]);
                As[r + rr][c + 0] = v.x;
                As[r + rr][c + 1] = v.y;
                As[r + rr][c + 2] = v.z;
                As[r + rr][c + 3] = v.w;
            }
        }
        {
            const int r = tid >> 4;
            const int c = (tid & 15) * 4;
#pragma unroll
            for (int rr = 0; rr < 32; rr += 16) {
                float4 v = *reinterpret_cast<const float4*>(
                    &W[(size_t)(k0 + r + rr) * 512 + n0 + c]);
                *reinterpret_cast<float4*>(&Bs[r + rr][c]) = v;
            }
        }
        __syncthreads();

#pragma unroll 8
        for (int kk = 0; kk < 32; kk++) {
            float a0 = As[ty * 4 + 0][kk];
            float a1 = As[ty * 4 + 1][kk];
            float a2 = As[ty * 4 + 2][kk];
            float a3 = As[ty * 4 + 3][kk];
            float4 b4 = *reinterpret_cast<const float4*>(&Bs[kk][tx * 4]);
            acc[0][0] += a0 * b4.x; acc[0][1] += a0 * b4.y; acc[0][2] += a0 * b4.z; acc[0][3] += a0 * b4.w;
            acc[1][0] += a1 * b4.x; acc[1][1] += a1 * b4.y; acc[1][2] += a1 * b4.z; acc[1][3] += a1 * b4.w;
            acc[2][0] += a2 * b4.x; acc[2][1] += a2 * b4.y; acc[2][2] += a2 * b4.z; acc[2][3] += a2 * b4.w;
            acc[3][0] += a3 * b4.x; acc[3][1] += a3 * b4.y; acc[3][2] += a3 * b4.z; acc[3][3] += a3 * b4.w;
        }
        __syncthreads();
    }

#pragma unroll
    for (int i = 0; i < 4; i++) {
        const int m = m0 + ty * 4 + i;
        float4 st;
        st.x = acc[i][0]; st.y = acc[i][1]; st.z = acc[i][2]; st.w = acc[i][3];
        *reinterpret_cast<float4*>(&Y[(size_t)m * 512 + n0 + tx * 4]) = st;
    }
}

// ---------------------------------------------------------------------------
extern "C" void kernel_launch(void* const* d_in, const int* in_sizes, int n_in,
                              void* d_out, int out_size)
{
    const float* q    = (const float*)d_in[0];
    const float* k    = (const float*)d_in[1];
    const float* v    = (const float*)d_in[2];
    const int*   mask = (const int*)d_in[3];
    const float* w_q  = (const float*)d_in[4];
    const float* w_k  = (const float*)d_in[5];
    const float* w_v  = (const float*)d_in[6];
    const float* w_o  = (const float*)d_in[7];
    float* out = (float*)d_out;

    cudaFuncSetAttribute(flash_mma_kernel,
                         cudaFuncAttributeMaxDynamicSharedMemorySize,
                         FL_SMEM_BYTES);

    dim3 gproj(128, 8);
    dim3 tproj(256);
    proj_qkv_kernel<<<gproj, tproj>>>(q, w_q, 0);
    proj_qkv_kernel<<<gproj, tproj>>>(k, w_k, 1);
    proj_qkv_kernel<<<gproj, tproj>>>(v, w_v, 2);

    dim3 gflash(S_ / 128, B_ * H_);
    flash_mma_kernel<<<gflash, 256, FL_SMEM_BYTES>>>(mask);

    out_proj_kernel<<<gproj, tproj>>>(w_o, out);
}

// round 9
// speedup vs baseline: 1.8089x; 1.0950x over previous
#include <cuda_runtime.h>
#include <cuda_bf16.h>
#include <cstdint>

// Problem constants
#define B_   2
#define S_   4096
#define D_   512
#define H_   8
#define DK_  64
#define BHS  (B_*H_*S_*DK_)

// Scratch (head layout [b][h][s][dk]); g_kh/g_vh hold tf32-rounded values.
__device__ float g_qh[BHS];
__device__ float g_kh[BHS];
__device__ float g_vh[BHS];
__device__ float g_oh[BHS];

// ---------------------------------------------------------------------------
// tf32 / cp.async helpers
// ---------------------------------------------------------------------------
__device__ __forceinline__ float tf32_rna(float x) {
    uint32_t u;
    asm("cvt.rna.tf32.f32 %0, %1;" : "=r"(u) : "f"(x));
    return __uint_as_float(u);
}

__device__ __forceinline__ void mma8(float* d,
                                     uint32_t a0, uint32_t a1, uint32_t a2, uint32_t a3,
                                     uint32_t b0, uint32_t b1) {
    asm volatile(
        "mma.sync.aligned.m16n8k8.row.col.f32.tf32.tf32.f32 "
        "{%0,%1,%2,%3}, {%4,%5,%6,%7}, {%8,%9}, {%0,%1,%2,%3};"
        : "+f"(d[0]), "+f"(d[1]), "+f"(d[2]), "+f"(d[3])
        : "r"(a0), "r"(a1), "r"(a2), "r"(a3), "r"(b0), "r"(b1));
}

__device__ __forceinline__ void cpa16(uint32_t s, const void* g) {
    asm volatile("cp.async.cg.shared.global [%0], [%1], 16;"
                 :: "r"(s), "l"(g) : "memory");
}
#define CPA_COMMIT()  asm volatile("cp.async.commit_group;" ::: "memory")
#define CPA_WAIT_1()  asm volatile("cp.async.wait_group 1;" ::: "memory")
#define CPA_WAIT_0()  asm volatile("cp.async.wait_group 0;" ::: "memory")

// Shared dynamic smem (cast per kernel)
extern __shared__ __align__(16) char smraw[];

// ---------------------------------------------------------------------------
// Unified projection kernel, 3-term tf32 MMA (near-fp32 accuracy).
// Y[8192,512] = X[8192,512] @ W[512,512].
// mode 0: X=q  -> g_qh (head layout, no rounding)
// mode 1: X=k  -> g_kh (head layout, tf32-rounded)
// mode 2: X=v  -> g_vh (head layout, tf32-rounded)
// mode 3: X=g_oh (head layout read) -> Y (flat [B*S, D])
// BM=128, BN=64, BK=32, 256 threads (8 warps), warp = 16 rows x 64 cols.
// ---------------------------------------------------------------------------
#define PA_STR 36   // float2 stride of A2 rows (36 mod 16 == 4 -> conflict-free)
#define PB_STR 68   // float2 stride of B2 rows (68 mod 16 == 4 -> conflict-free)
#define PROJ_SMEM_BYTES ((128*PA_STR + 32*PB_STR) * 8)

__global__ __launch_bounds__(256, 2) void proj_mma_kernel(const float* __restrict__ X,
                                                          const float* __restrict__ W,
                                                          float* __restrict__ Y,
                                                          int mode)
{
    float2* A2 = reinterpret_cast<float2*>(smraw);          // [128][PA_STR] (hi,lo)
    float2* B2 = A2 + 128 * PA_STR;                         // [32][PB_STR]  (hi,lo)

    const int tid  = threadIdx.x;
    const int wid  = tid >> 5;
    const int lane = tid & 31;
    const int g    = lane >> 2;
    const int tig  = lane & 3;
    const int m0   = blockIdx.x * 128;
    const int n0   = blockIdx.y * 64;

    float of[8][4];
#pragma unroll
    for (int nf = 0; nf < 8; nf++) { of[nf][0]=of[nf][1]=of[nf][2]=of[nf][3]=0.f; }

    const int ar = tid >> 3;          // A loader row 0..31
    const int ac = (tid & 7) * 4;     // A loader col 0..28
    const int br = tid >> 4;          // B loader row 0..15
    const int bc = (tid & 15) * 4;    // B loader col 0..60

    for (int k0 = 0; k0 < 512; k0 += 32) {
        __syncthreads();
        // ---- load A tile 128x32 (hi/lo split) ----
#pragma unroll
        for (int rr = 0; rr < 128; rr += 32) {
            const int m = m0 + rr + ar;
            const float* src;
            if (mode == 3) {
                const int b = m >> 12, s = m & 4095;
                const int h = k0 >> 6, dk = (k0 & 63) + ac;
                src = &g_oh[(((size_t)(b * H_ + h)) * S_ + s) * DK_ + dk];
            } else {
                src = &X[(size_t)m * 512 + k0 + ac];
            }
            float4 v = *reinterpret_cast<const float4*>(src);
            float2* dst = &A2[(rr + ar) * PA_STR + ac];
            float h0 = tf32_rna(v.x), h1 = tf32_rna(v.y);
            float h2 = tf32_rna(v.z), h3 = tf32_rna(v.w);
            dst[0] = make_float2(h0, tf32_rna(v.x - h0));
            dst[1] = make_float2(h1, tf32_rna(v.y - h1));
            dst[2] = make_float2(h2, tf32_rna(v.z - h2));
            dst[3] = make_float2(h3, tf32_rna(v.w - h3));
        }
        // ---- load B tile 32x64 (hi/lo split) ----
#pragma unroll
        for (int rr = 0; rr < 32; rr += 16) {
            float4 v = *reinterpret_cast<const float4*>(
                &W[(size_t)(k0 + rr + br) * 512 + n0 + bc]);
            float2* dst = &B2[(rr + br) * PB_STR + bc];
            float h0 = tf32_rna(v.x), h1 = tf32_rna(v.y);
            float h2 = tf32_rna(v.z), h3 = tf32_rna(v.w);
            dst[0] = make_float2(h0, tf32_rna(v.x - h0));
            dst[1] = make_float2(h1, tf32_rna(v.y - h1));
            dst[2] = make_float2(h2, tf32_rna(v.z - h2));
            dst[3] = make_float2(h3, tf32_rna(v.w - h3));
        }
        __syncthreads();

        // ---- 3-term tf32 MMA over this k-chunk ----
#pragma unroll
        for (int ks = 0; ks < 4; ks++) {
            const int arow = wid * 16 + g;
            const int acol = ks * 8 + tig;
            float2 a0 = A2[arow * PA_STR + acol];
            float2 a1 = A2[(arow + 8) * PA_STR + acol];
            float2 a2 = A2[arow * PA_STR + acol + 4];
            float2 a3 = A2[(arow + 8) * PA_STR + acol + 4];
            uint32_t ah0 = __float_as_uint(a0.x), al0 = __float_as_uint(a0.y);
            uint32_t ah1 = __float_as_uint(a1.x), al1 = __float_as_uint(a1.y);
            uint32_t ah2 = __float_as_uint(a2.x), al2 = __float_as_uint(a2.y);
            uint32_t ah3 = __float_as_uint(a3.x), al3 = __float_as_uint(a3.y);
#pragma unroll
            for (int nf = 0; nf < 8; nf++) {
                float2 b0 = B2[(ks * 8 + tig) * PB_STR + nf * 8 + g];
                float2 b1 = B2[(ks * 8 + tig + 4) * PB_STR + nf * 8 + g];
                uint32_t bh0 = __float_as_uint(b0.x), bl0 = __float_as_uint(b0.y);
                uint32_t bh1 = __float_as_uint(b1.x), bl1 = __float_as_uint(b1.y);
                mma8(of[nf], ah0, ah1, ah2, ah3, bh0, bh1);
                mma8(of[nf], al0, al1, al2, al3, bh0, bh1);
                mma8(of[nf], ah0, ah1, ah2, ah3, bl0, bl1);
            }
        }
    }

    // ---- epilogue ----
    const int row = m0 + wid * 16 + g;     // and row+8
    if (mode == 3) {
#pragma unroll
        for (int nf = 0; nf < 8; nf++) {
            const int n = n0 + nf * 8 + 2 * tig;
            *reinterpret_cast<float2*>(&Y[(size_t)row * 512 + n]) =
                make_float2(of[nf][0], of[nf][1]);
            *reinterpret_cast<float2*>(&Y[(size_t)(row + 8) * 512 + n]) =
                make_float2(of[nf][2], of[nf][3]);
        }
    } else {
        float* Oh = (mode == 0) ? g_qh : (mode == 1) ? g_kh : g_vh;
        const bool rnd = (mode != 0);
        const int h = blockIdx.y;          // n0>>6, BN==64
        const int b0r = row >> 12, s0r = row & 4095;
#pragma unroll
        for (int nf = 0; nf < 8; nf++) {
            const int dk = nf * 8 + 2 * tig;
            float v0 = of[nf][0], v1 = of[nf][1], v2 = of[nf][2], v3 = of[nf][3];
            if (rnd) { v0 = tf32_rna(v0); v1 = tf32_rna(v1); v2 = tf32_rna(v2); v3 = tf32_rna(v3); }
            *reinterpret_cast<float2*>(
                &Oh[(((size_t)(b0r * H_ + h)) * S_ + s0r) * DK_ + dk]) = make_float2(v0, v1);
            const int row1 = row + 8;
            const int b1r = row1 >> 12, s1r = row1 & 4095;
            *reinterpret_cast<float2*>(
                &Oh[(((size_t)(b1r * H_ + h)) * S_ + s1r) * DK_ + dk]) = make_float2(v2, v3);
        }
    }
}

// ---------------------------------------------------------------------------
// Flash attention v3: tf32 mma, cp.async double-buffered K/V (pre-rounded in
// gmem -> ZERO conversions in the hot loop). BQ=128, BK=64, DK=64, 8 warps.
// QK^T: 2-term (q hi/lo x k_tf32); PV: single term (P rna'd, V pre-rounded).
// ---------------------------------------------------------------------------
#define KR_STR 68   // K: bank = 4g + tig for B-frag loads  -> conflict-free
#define VR_STR 72   // V: bank = 8tig + g                   -> conflict-free
#define PS_STR 76   // P: bank = 12g + tig                  -> conflict-free

#define SM_K   0
#define SM_V   (2*64*KR_STR)
#define SM_P   (SM_V + 2*64*VR_STR)
#define FL_SMEM_FLOATS (SM_P + 128*PS_STR)
#define FL_SMEM_BYTES  (FL_SMEM_FLOATS * 4)
#define NT     (S_/64)

__global__ __launch_bounds__(256, 1) void flash_mma_kernel(const int* __restrict__ mask)
{
    float* sm = reinterpret_cast<float*>(smraw);
    float* Kr = sm + SM_K;      // [2][64][KR_STR]
    float* Vr = sm + SM_V;      // [2][64][VR_STR]
    float* Ps = sm + SM_P;      // [128][PS_STR]
    const uint32_t k_u32 = (uint32_t)__cvta_generic_to_shared(Kr);
    const uint32_t v_u32 = (uint32_t)__cvta_generic_to_shared(Vr);

    const int tid  = threadIdx.x;
    const int wid  = tid >> 5;
    const int lane = tid & 31;
    const int g    = lane >> 2;
    const int tig  = lane & 3;
    const int bh   = blockIdx.y;
    const int b    = bh >> 3;
    const int q0   = blockIdx.x * 128;

    const int r0 = wid * 16 + g;

    const float* Kp = g_kh + (size_t)bh * S_ * DK_;
    const float* Vp = g_vh + (size_t)bh * S_ * DK_;

    const int lr = tid >> 4;         // loader row 0..15
    const int lc = (tid & 15) * 4;   // loader col (floats)

    // --- Q fragments (hi/lo) resident in registers ---
    uint32_t qhi[8][4], qlo[8][4];
    {
        const float* Q0 = g_qh + ((size_t)bh * S_ + q0 + r0) * DK_;
        const float* Q1 = Q0 + 8 * DK_;
#pragma unroll
        for (int ks = 0; ks < 8; ks++) {
            float x0 = Q0[ks*8 + tig],     x1 = Q1[ks*8 + tig];
            float x2 = Q0[ks*8 + tig + 4], x3 = Q1[ks*8 + tig + 4];
            float h;
            h = tf32_rna(x0); qhi[ks][0] = __float_as_uint(h); qlo[ks][0] = __float_as_uint(tf32_rna(x0 - h));
            h = tf32_rna(x1); qhi[ks][1] = __float_as_uint(h); qlo[ks][1] = __float_as_uint(tf32_rna(x1 - h));
            h = tf32_rna(x2); qhi[ks][2] = __float_as_uint(h); qlo[ks][2] = __float_as_uint(tf32_rna(x2 - h));
            h = tf32_rna(x3); qhi[ks][3] = __float_as_uint(h); qlo[ks][3] = __float_as_uint(tf32_rna(x3 - h));
        }
    }

    const int* Mp0 = mask + ((size_t)b * S_ + q0 + r0) * S_;
    const int* Mp1 = Mp0 + 8 * S_;

    float of[8][4];
#pragma unroll
    for (int nf = 0; nf < 8; nf++) { of[nf][0]=of[nf][1]=of[nf][2]=of[nf][3]=0.f; }
    float m0 = -INFINITY, m1 = -INFINITY, l0 = 0.f, l1 = 0.f;

    // Prologue: issue tile 0 into buffer 0
    {
        const float* Kg = Kp + (size_t)lr * DK_ + lc;
        const float* Vg = Vp + (size_t)lr * DK_ + lc;
#pragma unroll
        for (int rr = 0; rr < 64; rr += 16) {
            cpa16(k_u32 + (uint32_t)(((rr + lr) * KR_STR + lc) * 4), Kg + (size_t)rr * DK_);
            cpa16(v_u32 + (uint32_t)(((rr + lr) * VR_STR + lc) * 4), Vg + (size_t)rr * DK_);
        }
        CPA_COMMIT();
    }

    for (int t = 0; t < NT; t++) {
        const int buf = t & 1;
        __syncthreads();   // all warps done with buf^1 contents (tile t-1 PV)

        if (t + 1 < NT) {
            const int nb = buf ^ 1;
            const float* Kg = Kp + (size_t)((t + 1) * 64 + lr) * DK_ + lc;
            const float* Vg = Vp + (size_t)((t + 1) * 64 + lr) * DK_ + lc;
#pragma unroll
            for (int rr = 0; rr < 64; rr += 16) {
                cpa16(k_u32 + (uint32_t)(((nb * 64 + rr + lr) * KR_STR + lc) * 4), Kg + (size_t)rr * DK_);
                cpa16(v_u32 + (uint32_t)(((nb * 64 + rr + lr) * VR_STR + lc) * 4), Vg + (size_t)rr * DK_);
            }
            CPA_COMMIT();
            CPA_WAIT_1();   // tile t done, tile t+1 may still fly
        } else {
            CPA_WAIT_0();
        }
        __syncthreads();   // tile-t data (copied by other threads) visible

        const float* Kb = Kr + buf * 64 * KR_STR;
        const float* Vb = Vr + buf * 64 * VR_STR;
        const int k0 = t * 64;

        // Prefetch mask into registers (latency hides under QK MMAs)
        int2 ma[8], mb[8];
#pragma unroll
        for (int nf = 0; nf < 8; nf++) {
            const int col = k0 + nf * 8 + 2 * tig;
            ma[nf] = *reinterpret_cast<const int2*>(&Mp0[col]);
            mb[nf] = *reinterpret_cast<const int2*>(&Mp1[col]);
        }

        // ---- S = Q @ K^T  (2-term, K pre-rounded: NO conversions here) ----
        float sf[8][4];
#pragma unroll
        for (int nf = 0; nf < 8; nf++) { sf[nf][0]=sf[nf][1]=sf[nf][2]=sf[nf][3]=0.f; }

#pragma unroll
        for (int ks = 0; ks < 8; ks++) {
            const int kcol = ks * 8 + tig;
#pragma unroll
            for (int nf = 0; nf < 8; nf++) {
                const int krow = nf * 8 + g;
                uint32_t bh0 = __float_as_uint(Kb[krow * KR_STR + kcol]);
                uint32_t bh1 = __float_as_uint(Kb[krow * KR_STR + kcol + 4]);
                mma8(sf[nf], qhi[ks][0], qhi[ks][1], qhi[ks][2], qhi[ks][3], bh0, bh1);
                mma8(sf[nf], qlo[ks][0], qlo[ks][1], qlo[ks][2], qlo[ks][3], bh0, bh1);
            }
        }

        // ---- mask + scale + online softmax ----
        const float NEG = -1e9f;
        float mt0 = -INFINITY, mt1 = -INFINITY;
#pragma unroll
        for (int nf = 0; nf < 8; nf++) {
            sf[nf][0] = ma[nf].x ? sf[nf][0] * 0.125f : NEG;
            sf[nf][1] = ma[nf].y ? sf[nf][1] * 0.125f : NEG;
            sf[nf][2] = mb[nf].x ? sf[nf][2] * 0.125f : NEG;
            sf[nf][3] = mb[nf].y ? sf[nf][3] * 0.125f : NEG;
            mt0 = fmaxf(mt0, fmaxf(sf[nf][0], sf[nf][1]));
            mt1 = fmaxf(mt1, fmaxf(sf[nf][2], sf[nf][3]));
        }
        mt0 = fmaxf(mt0, __shfl_xor_sync(0xffffffffu, mt0, 1));
        mt0 = fmaxf(mt0, __shfl_xor_sync(0xffffffffu, mt0, 2));
        mt1 = fmaxf(mt1, __shfl_xor_sync(0xffffffffu, mt1, 1));
        mt1 = fmaxf(mt1, __shfl_xor_sync(0xffffffffu, mt1, 2));

        const float mn0 = fmaxf(m0, mt0), mn1 = fmaxf(m1, mt1);
        const float al0 = __expf(m0 - mn0), al1 = __expf(m1 - mn1);
        m0 = mn0; m1 = mn1;

        float rs0 = 0.f, rs1 = 0.f;
        float* P0 = &Ps[r0 * PS_STR];
        float* P1 = &Ps[(r0 + 8) * PS_STR];
#pragma unroll
        for (int nf = 0; nf < 8; nf++) {
            float p0 = __expf(sf[nf][0] - m0), p1 = __expf(sf[nf][1] - m0);
            float p2 = __expf(sf[nf][2] - m1), p3 = __expf(sf[nf][3] - m1);
            rs0 += p0 + p1; rs1 += p2 + p3;
            float2 q01 = {tf32_rna(p0), tf32_rna(p1)};
            float2 q23 = {tf32_rna(p2), tf32_rna(p3)};
            *reinterpret_cast<float2*>(&P0[nf * 8 + 2 * tig]) = q01;
            *reinterpret_cast<float2*>(&P1[nf * 8 + 2 * tig]) = q23;
        }
        rs0 += __shfl_xor_sync(0xffffffffu, rs0, 1);
        rs0 += __shfl_xor_sync(0xffffffffu, rs0, 2);
        rs1 += __shfl_xor_sync(0xffffffffu, rs1, 1);
        rs1 += __shfl_xor_sync(0xffffffffu, rs1, 2);
        l0 = l0 * al0 + rs0;
        l1 = l1 * al1 + rs1;
#pragma unroll
        for (int nf = 0; nf < 8; nf++) {
            of[nf][0] *= al0; of[nf][1] *= al0;
            of[nf][2] *= al1; of[nf][3] *= al1;
        }
        __syncwarp();   // P rows are warp-private: warp-level sync suffices

        // ---- O += P @ V  (single tf32, V pre-rounded: NO conversions) ----
#pragma unroll
        for (int ks = 0; ks < 8; ks++) {
            uint32_t a0 = __float_as_uint(Ps[r0 * PS_STR + ks * 8 + tig]);
            uint32_t a1 = __float_as_uint(Ps[(r0 + 8) * PS_STR + ks * 8 + tig]);
            uint32_t a2 = __float_as_uint(Ps[r0 * PS_STR + ks * 8 + tig + 4]);
            uint32_t a3 = __float_as_uint(Ps[(r0 + 8) * PS_STR + ks * 8 + tig + 4]);
#pragma unroll
            for (int nf = 0; nf < 8; nf++) {
                uint32_t b0 = __float_as_uint(Vb[(ks * 8 + tig) * VR_STR + nf * 8 + g]);
                uint32_t b1 = __float_as_uint(Vb[(ks * 8 + tig + 4) * VR_STR + nf * 8 + g]);
                mma8(of[nf], a0, a1, a2, a3, b0, b1);
            }
        }
    }

    // ---- epilogue: normalize + store ----
    const float inv0 = 1.f / l0, inv1 = 1.f / l1;
    float* O0 = g_oh + ((size_t)bh * S_ + q0 + r0) * DK_;
    float* O1 = O0 + 8 * DK_;
#pragma unroll
    for (int nf = 0; nf < 8; nf++) {
        float2 o01 = {of[nf][0] * inv0, of[nf][1] * inv0};
        float2 o23 = {of[nf][2] * inv1, of[nf][3] * inv1};
        *reinterpret_cast<float2*>(&O0[nf * 8 + 2 * tig]) = o01;
        *reinterpret_cast<float2*>(&O1[nf * 8 + 2 * tig]) = o23;
    }
}

// ---------------------------------------------------------------------------
extern "C" void kernel_launch(void* const* d_in, const int* in_sizes, int n_in,
                              void* d_out, int out_size)
{
    const float* q    = (const float*)d_in[0];
    const float* k    = (const float*)d_in[1];
    const float* v    = (const float*)d_in[2];
    const int*   mask = (const int*)d_in[3];
    const float* w_q  = (const float*)d_in[4];
    const float* w_k  = (const float*)d_in[5];
    const float* w_v  = (const float*)d_in[6];
    const float* w_o  = (const float*)d_in[7];
    float* out = (float*)d_out;

    cudaFuncSetAttribute(flash_mma_kernel,
                         cudaFuncAttributeMaxDynamicSharedMemorySize,
                         FL_SMEM_BYTES);
    cudaFuncSetAttribute(proj_mma_kernel,
                         cudaFuncAttributeMaxDynamicSharedMemorySize,
                         PROJ_SMEM_BYTES);

    dim3 gproj(64, 8);
    dim3 tproj(256);
    proj_mma_kernel<<<gproj, tproj, PROJ_SMEM_BYTES>>>(q, w_q, nullptr, 0);
    proj_mma_kernel<<<gproj, tproj, PROJ_SMEM_BYTES>>>(k, w_k, nullptr, 1);
    proj_mma_kernel<<<gproj, tproj, PROJ_SMEM_BYTES>>>(v, w_v, nullptr, 2);

    dim3 gflash(S_ / 128, B_ * H_);
    flash_mma_kernel<<<gflash, 256, FL_SMEM_BYTES>>>(mask);

    proj_mma_kernel<<<gproj, tproj, PROJ_SMEM_BYTES>>>(nullptr, w_o, out, 3);
}